// round 15
// baseline (speedup 1.0000x reference)
#include <cuda_runtime.h>
#include <cuda_fp16.h>
#include <cuda_fp8.h>
#include <cstdint>

#define HDIM 4096
#define MTOK 4096

// ---------------- scratch (device globals; no runtime alloc) ----------------
__device__ float  g_resid[(size_t)MTOK * HDIM];    // 64 MB (GEMM accumulates here)
__device__ __half g_A[(size_t)MTOK * HDIM];        // 32 MB  qdq activations, fp16
__device__ __half g_WT[3][(size_t)HDIM * HDIM];    // 96 MB  scaled weights, [N,K] K-major

// ---------------- PTX helpers (plain compute_103-legal) ----------------
__device__ __forceinline__ uint32_t smem_u32(const void* p) {
    uint32_t a;
    asm("{ .reg .u64 t; cvta.to.shared.u64 t, %1; cvt.u32.u64 %0, t; }" : "=r"(a) : "l"(p));
    return a;
}
__device__ __forceinline__ void cp16(uint32_t s, const void* g) {
    asm volatile("cp.async.cg.shared.global [%0], [%1], 16;" :: "r"(s), "l"(g));
}
__device__ __forceinline__ void ldsm4(uint32_t& r0, uint32_t& r1, uint32_t& r2, uint32_t& r3,
                                      uint32_t addr) {
    asm volatile("ldmatrix.sync.aligned.m8n8.x4.shared.b16 {%0,%1,%2,%3}, [%4];"
                 : "=r"(r0), "=r"(r1), "=r"(r2), "=r"(r3) : "r"(addr));
}
__device__ __forceinline__ void mma16816(float* c, const uint32_t* a, const uint32_t* b) {
    asm volatile("mma.sync.aligned.m16n8k16.row.col.f32.f16.f16.f32 "
                 "{%0,%1,%2,%3}, {%4,%5,%6,%7}, {%8,%9}, {%0,%1,%2,%3};"
                 : "+f"(c[0]), "+f"(c[1]), "+f"(c[2]), "+f"(c[3])
                 : "r"(a[0]), "r"(a[1]), "r"(a[2]), "r"(a[3]), "r"(b[0]), "r"(b[1]));
}

#define MBARRIER_INIT(addr, cnt) \
    asm volatile("mbarrier.init.shared.b64 [%0], %1;" :: "r"((uint32_t)(addr)), "r"((uint32_t)(cnt)) : "memory")
#define MBARRIER_ARRIVE(addr) \
    asm volatile("mbarrier.arrive.shared.b64 _, [%0];" :: "r"((uint32_t)(addr)) : "memory")
#define CP_ARRIVE(addr) \
    asm volatile("cp.async.mbarrier.arrive.noinc.shared::cta.b64 [%0];" :: "r"((uint32_t)(addr)) : "memory")

#define MBARRIER_WAIT_PARITY(mbar_smem_addr, phase_parity) do { \
    uint32_t _mbar = (uint32_t)(mbar_smem_addr); \
    uint32_t _parity = (uint32_t)(phase_parity); \
    uint32_t _done; \
    asm volatile( \
        "{\n\t" \
        ".reg .pred p;\n\t" \
        "mbarrier.try_wait.parity.acquire.cta.shared::cta.b64 p, [%1], %2;\n\t" \
        "selp.b32 %0, 1, 0, p;\n\t" \
        "}" \
        : "=r"(_done) : "r"(_mbar), "r"(_parity) : "memory"); \
    if (!_done) { \
        asm volatile( \
            "{\n\t" \
            ".reg .pred P1;\n\t" \
            "WAIT_LOOP_%=:\n\t" \
            "mbarrier.try_wait.parity.acquire.cta.shared::cta.b64 P1, [%0], %1, 0x989680;\n\t" \
            "@P1 bra.uni WAIT_DONE_%=;\n\t" \
            "bra.uni WAIT_LOOP_%=;\n\t" \
            "WAIT_DONE_%=:\n\t" \
            "}" \
            :: "r"(_mbar), "r"(_parity) : "memory"); \
    } \
} while(0)

// ---------------- wdq tile: 64x64 transpose + scale + fp16 cast --------------
__device__ __forceinline__ int wswz(int r, int c) {
    return c ^ (((((r >> 4)) ^ (r & 1)) & 3) << 3) ^ ((c & 32) >> 3);
}
__device__ __forceinline__ void wdq_tile(const float* __restrict__ w,
                                         const float* __restrict__ ws,
                                         __half* __restrict__ dst,
                                         int tile, float* tileS) {
    const int t  = threadIdx.x;
    const int n0 = (tile & 63) << 6, k0 = (tile >> 6) << 6;
    const float s = ws[(k0 >> 7) * 32 + (n0 >> 7)];
    if (t < 256) {
        const int kr = t >> 2, c = (t & 3) << 4;
        const float* src = w + (size_t)(k0 + kr) * HDIM + n0 + c;
#pragma unroll
        for (int j = 0; j < 4; ++j) {
            float4 v = *reinterpret_cast<const float4*>(src + 4 * j);
            *reinterpret_cast<float4*>(&tileS[kr * 64 + wswz(kr, c + 4 * j)]) = v;
        }
    }
    __syncthreads();
    if (t < 256) {
        const int n = t >> 2, kc = (t & 3) << 4;
        __half2 hv[8];
#pragma unroll
        for (int u = 0; u < 8; ++u) {
            const int r0 = kc + 2 * u, r1 = r0 + 1;
            hv[u] = __floats2half2_rn(tileS[r0 * 64 + wswz(r0, n)] * s,
                                      tileS[r1 * 64 + wswz(r1, n)] * s);
        }
        uint4* dp = reinterpret_cast<uint4*>(dst + (size_t)(n0 + n) * HDIM + k0 + kc);
        const uint4* hv4 = reinterpret_cast<const uint4*>(hv);
        dp[0] = hv4[0];
        dp[1] = hv4[1];
    }
}

// ------- GEMM: g_resid += g_A @ g_WT[w]^T. BM=BN=128, BK=32, 5-stage mbar ring
// full[s] @ sb+8s (256 arrivals, cp.async-tracked); empty[s] @ sb+64+8s (8 warps)
static constexpr int      BK = 32, STAGES = 5;
static constexpr int      NIT = HDIM / BK;                    // 128
static constexpr int      SW  = 40;                           // smem stride (halfs)
static constexpr uint32_t DATA_OFF  = 1024;
static constexpr uint32_t ABYTES    = 128 * SW * 2;           // 10240
static constexpr uint32_t STG_BYTES = 2 * ABYTES;             // 20480 (A + B)
static constexpr uint32_t GEMM_SMEM = DATA_OFF + STAGES * STG_BYTES;  // 103424
static constexpr int      NGEMM_CTAS = 1024;

__global__ void __launch_bounds__(256, 2) gemm_kernel(int which,
                                                      const float* __restrict__ wn,
                                                      const float* __restrict__ wsn) {
    extern __shared__ __half smem[];
    if (blockIdx.x >= NGEMM_CTAS) {
        wdq_tile(wn, wsn, g_WT[which + 1], blockIdx.x - NGEMM_CTAS,
                 reinterpret_cast<float*>(smem));
        return;
    }
    const uint32_t sb = smem_u32(smem);
    const int tid  = threadIdx.x;
    const int lane = tid & 31;
    const int warp = tid >> 5;
    const int m0 = (blockIdx.x >> 5) << 7;   // 32 m-panels
    const int n0 = (blockIdx.x & 31) << 7;   // 32 n-panels
    const int wm = warp & 3;                 // 4 warps along M (32 rows each)
    const int wn2 = warp >> 2;               // 2 warps along N (64 cols each)

    if (tid == 0) {
#pragma unroll
        for (int s = 0; s < STAGES; ++s) {
            MBARRIER_INIT(sb + 8 * s, 256);       // full[s]
            MBARRIER_INIT(sb + 64 + 8 * s, 8);    // empty[s]
        }
    }
    __syncthreads();

    // per-warp producer slice
    const int prow = warp * 16 + (lane >> 1);
    const int pj   = (lane & 1) * 2;
    const __half* gA = g_A + (size_t)(m0 + prow) * HDIM + pj * 8;
    const __half* gB = g_WT[which] + (size_t)(n0 + prow) * HDIM + pj * 8;
    const uint32_t sA = sb + DATA_OFF + (uint32_t)((prow * SW + pj * 8) * 2);
    const uint32_t sB = sA + ABYTES;

#define LOAD_STAGE(it, s) do { \
        const uint32_t _so = (uint32_t)(s) * STG_BYTES; \
        const __half* _a = gA + (size_t)(it) * BK; \
        const __half* _b = gB + (size_t)(it) * BK; \
        cp16(sA + _so,       _a);      \
        cp16(sA + _so + 16,  _a + 8);  \
        cp16(sB + _so,       _b);      \
        cp16(sB + _so + 16,  _b + 8);  \
        CP_ARRIVE(sb + 8 * (s));       \
    } while (0)

    // prologue: produce stages 0..3 (round 0, no empty wait)
    LOAD_STAGE(0, 0);
    LOAD_STAGE(1, 1);
    LOAD_STAGE(2, 2);
    LOAD_STAGE(3, 3);

    float c[2][8][4];
#pragma unroll
    for (int mi = 0; mi < 2; ++mi)
#pragma unroll
        for (int ni = 0; ni < 8; ++ni)
#pragma unroll
            for (int v = 0; v < 4; ++v) c[mi][ni][v] = 0.f;

    // consumer fragment base addresses (stage 0)
    const uint32_t aBase = sb + DATA_OFF +
        (uint32_t)(((wm * 32 + (lane & 15)) * SW + (lane >> 4) * 8) * 2);
    const uint32_t bBase = sb + DATA_OFF + ABYTES +
        (uint32_t)(((wn2 * 64 + ((lane >> 4) & 1) * 8 + (lane & 7)) * SW + ((lane >> 3) & 1) * 8) * 2);

    int cs = 0, cph = 0;          // consumer stage / phase
    int ps = 4, pround = 0;       // producer stage / round

#pragma unroll 1
    for (int it = 0; it < NIT; ++it) {
        // ---- produce early: stage for iteration it+4 ----
        const int p = it + 4;
        if (p < NIT) {
            if (pround > 0) MBARRIER_WAIT_PARITY(sb + 64 + 8 * ps, (pround - 1) & 1);
            LOAD_STAGE(p, ps);
            if (++ps == STAGES) { ps = 0; ++pround; }
        }

        // ---- consume stage cs ----
        MBARRIER_WAIT_PARITY(sb + 8 * cs, cph);
        const uint32_t so = (uint32_t)cs * STG_BYTES;

        uint32_t a[2][4], b[8][2];
        // ks = 0
#pragma unroll
        for (int mi = 0; mi < 2; ++mi)
            ldsm4(a[mi][0], a[mi][1], a[mi][2], a[mi][3],
                  aBase + so + (uint32_t)(mi * 16 * SW * 2));
#pragma unroll
        for (int pz = 0; pz < 4; ++pz)
            ldsm4(b[2 * pz][0], b[2 * pz][1], b[2 * pz + 1][0], b[2 * pz + 1][1],
                  bBase + so + (uint32_t)(pz * 16 * SW * 2));
#pragma unroll
        for (int mi = 0; mi < 2; ++mi)
#pragma unroll
            for (int ni = 0; ni < 8; ++ni)
                mma16816(c[mi][ni], a[mi], b[ni]);
        // ks = 1
#pragma unroll
        for (int mi = 0; mi < 2; ++mi)
            ldsm4(a[mi][0], a[mi][1], a[mi][2], a[mi][3],
                  aBase + so + (uint32_t)(mi * 16 * SW * 2 + 32));
#pragma unroll
        for (int pz = 0; pz < 4; ++pz)
            ldsm4(b[2 * pz][0], b[2 * pz][1], b[2 * pz + 1][0], b[2 * pz + 1][1],
                  bBase + so + (uint32_t)(pz * 16 * SW * 2 + 32));
        // release early: all data for this stage now in registers
        __syncwarp();
        if (lane == 0) MBARRIER_ARRIVE(sb + 64 + 8 * cs);
#pragma unroll
        for (int mi = 0; mi < 2; ++mi)
#pragma unroll
            for (int ni = 0; ni < 8; ++ni)
                mma16816(c[mi][ni], a[mi], b[ni]);

        if (++cs == STAGES) { cs = 0; cph ^= 1; }
    }

    // epilogue: g_resid += acc (fused residual add)
#pragma unroll
    for (int mi = 0; mi < 2; ++mi) {
        const int row = m0 + wm * 32 + mi * 16 + (lane >> 2);
        float* b0 = g_resid + (size_t)row * HDIM + n0 + wn2 * 64 + 2 * (lane & 3);
        float* b1 = b0 + 8 * HDIM;
#pragma unroll
        for (int ni = 0; ni < 8; ++ni) {
            float2 o0 = *reinterpret_cast<float2*>(b0 + ni * 8);
            float2 o1 = *reinterpret_cast<float2*>(b1 + ni * 8);
            o0.x += c[mi][ni][0]; o0.y += c[mi][ni][1];
            o1.x += c[mi][ni][2]; o1.y += c[mi][ni][3];
            *reinterpret_cast<float2*>(b0 + ni * 8) = o0;
            *reinterpret_cast<float2*>(b1 + ni * 8) = o1;
        }
    }
#undef LOAD_STAGE
}

// -------- norm body: 512 threads, 8 elems/thread ------------------------------
__device__ __forceinline__ void norm_body(const float* __restrict__ xin,
                                          const float* __restrict__ nw,
                                          float* __restrict__ outp, int mode,
                                          int row, float* red) {
    const int t = threadIdx.x;
    const size_t base = (size_t)row * HDIM + t * 8;
    float4 va[2];
    float ss = 0.f;
    if (mode == 0) {
        const float4* px = reinterpret_cast<const float4*>(xin + base);
        float4* pr = reinterpret_cast<float4*>(g_resid + base);
#pragma unroll
        for (int i = 0; i < 2; ++i) {
            float4 a = px[i];
            a.x = fmaxf(a.x, 0.f); a.y = fmaxf(a.y, 0.f);
            a.z = fmaxf(a.z, 0.f); a.w = fmaxf(a.w, 0.f);
            va[i] = a; pr[i] = a;
            ss += a.x * a.x + a.y * a.y + a.z * a.z + a.w * a.w;
        }
    } else {
        const float4* pr = reinterpret_cast<const float4*>(g_resid + base);
#pragma unroll
        for (int i = 0; i < 2; ++i) {
            float4 a = pr[i];
            va[i] = a;
            ss += a.x * a.x + a.y * a.y + a.z * a.z + a.w * a.w;
        }
    }
#pragma unroll
    for (int o = 16; o; o >>= 1) ss += __shfl_down_sync(0xffffffffu, ss, o);
    if ((t & 31) == 0) red[t >> 5] = ss;
    __syncthreads();
    if (t == 0) {
        float s = 0.f;
#pragma unroll
        for (int i = 0; i < 16; ++i) s += red[i];
        red[16] = rsqrtf(s * (1.f / HDIM) + 1e-6f);
    }
    __syncthreads();
    const float r = red[16];

    const float4* pn = reinterpret_cast<const float4*>(nw) + t * 2;
    float y[8];
    float amax = 0.f;
#pragma unroll
    for (int i = 0; i < 2; ++i) {
        float4 a = va[i], w4 = pn[i];
        y[4 * i + 0] = a.x * r * w4.x; y[4 * i + 1] = a.y * r * w4.y;
        y[4 * i + 2] = a.z * r * w4.z; y[4 * i + 3] = a.w * r * w4.w;
        amax = fmaxf(amax, fabsf(y[4 * i + 0])); amax = fmaxf(amax, fabsf(y[4 * i + 1]));
        amax = fmaxf(amax, fabsf(y[4 * i + 2])); amax = fmaxf(amax, fabsf(y[4 * i + 3]));
    }
    if (mode == 2) {
        float4* po = reinterpret_cast<float4*>(outp + base);
        po[0] = make_float4(y[0], y[1], y[2], y[3]);
        po[1] = make_float4(y[4], y[5], y[6], y[7]);
        return;
    }
    amax = fmaxf(amax, __shfl_xor_sync(0xffffffffu, amax, 1));
    amax = fmaxf(amax, __shfl_xor_sync(0xffffffffu, amax, 2));
    amax = fmaxf(amax, __shfl_xor_sync(0xffffffffu, amax, 4));
    amax = fmaxf(amax, __shfl_xor_sync(0xffffffffu, amax, 8));
    const float amc = fmaxf(amax, 4.48e-10f);
    const float s  = amc * (1.f / 448.f);
    const float rs = __fdividef(448.f, amc);
    __half2 hv[4];
#pragma unroll
    for (int j = 0; j < 4; ++j) {
        float2 q = make_float2(y[2 * j] * rs, y[2 * j + 1] * rs);
        __nv_fp8x2_storage_t q2 = __nv_cvt_float2_to_fp8x2(q, __NV_SATFINITE, __NV_E4M3);
        __half2_raw hr = __nv_cvt_fp8x2_to_halfraw2(q2, __NV_E4M3);
        __half2 hq = *reinterpret_cast<__half2*>(&hr);
        float2 qf = __half22float2(hq);
        hv[j] = __floats2half2_rn(qf.x * s, qf.y * s);
    }
    *reinterpret_cast<uint4*>(g_A + base) = *reinterpret_cast<const uint4*>(hv);
}

// standalone norm (modes 1, 2), 512 threads
__global__ void __launch_bounds__(512) k_norm(const float* __restrict__ nw,
                                              float* __restrict__ outp, int mode) {
    __shared__ float red[17];
    norm_body(nullptr, nw, outp, mode, blockIdx.x, red);
}

// merged: norm mode0 (blocks 0..4095, 512 thr) + wdq(w0) (blocks 4096..8191)
__global__ void __launch_bounds__(512) k_norm0_wdq(const float* __restrict__ x,
                                                   const float* __restrict__ nw,
                                                   const float* __restrict__ w,
                                                   const float* __restrict__ ws) {
    __shared__ float sh[64 * 64];
    if (blockIdx.x < 4096) {
        norm_body(x, nw, nullptr, 0, blockIdx.x, sh);
    } else {
        wdq_tile(w, ws, g_WT[0], blockIdx.x - 4096, sh);
    }
}

// ---------------- launch ----------------
extern "C" void kernel_launch(void* const* d_in, const int* in_sizes, int n_in,
                              void* d_out, int out_size) {
    const float* x   = (const float*)d_in[0];
    const float* w0  = (const float*)d_in[1];
    const float* ws0 = (const float*)d_in[2];
    const float* w1  = (const float*)d_in[3];
    const float* ws1 = (const float*)d_in[4];
    const float* w2  = (const float*)d_in[5];
    const float* ws2 = (const float*)d_in[6];
    const float* nw0 = (const float*)d_in[7];
    const float* nw1 = (const float*)d_in[8];
    const float* nw2 = (const float*)d_in[9];
    const float* nw3 = (const float*)d_in[10];
    float* out = (float*)d_out;

    cudaFuncSetAttribute(gemm_kernel, cudaFuncAttributeMaxDynamicSharedMemorySize, GEMM_SMEM);

    k_norm0_wdq<<<8192, 512>>>(x, nw0, w0, ws0);                      // norm0 || wdq(w0)
    gemm_kernel<<<NGEMM_CTAS + 4096, 256, GEMM_SMEM>>>(0, w1, ws1);   // gemm0 + wdq(w1)

    k_norm<<<MTOK, 512>>>(nw1, nullptr, 1);
    gemm_kernel<<<NGEMM_CTAS + 4096, 256, GEMM_SMEM>>>(1, w2, ws2);   // gemm1 + wdq(w2)

    k_norm<<<MTOK, 512>>>(nw2, nullptr, 1);
    gemm_kernel<<<NGEMM_CTAS, 256, GEMM_SMEM>>>(2, nullptr, nullptr); // gemm2 only

    k_norm<<<MTOK, 512>>>(nw3, out, 2);
}

// round 16
// speedup vs baseline: 1.1237x; 1.1237x over previous
#include <cuda_runtime.h>
#include <cuda_fp16.h>
#include <cuda_fp8.h>
#include <cstdint>

#define HDIM 4096
#define MTOK 4096

// ---------------- scratch (device globals; no runtime alloc) ----------------
__device__ float  g_resid[(size_t)MTOK * HDIM];    // 64 MB (GEMM accumulates here)
__device__ __half g_A[(size_t)MTOK * HDIM];        // 32 MB  qdq activations, fp16
__device__ __half g_WT[3][(size_t)HDIM * HDIM];    // 96 MB  scaled weights, [N,K] K-major

// ---------------- PTX helpers (plain compute_103-legal) ----------------
__device__ __forceinline__ uint32_t smem_u32(const void* p) {
    uint32_t a;
    asm("{ .reg .u64 t; cvta.to.shared.u64 t, %1; cvt.u32.u64 %0, t; }" : "=r"(a) : "l"(p));
    return a;
}
__device__ __forceinline__ void cp16(uint32_t s, const void* g) {
    asm volatile("cp.async.cg.shared.global [%0], [%1], 16;" :: "r"(s), "l"(g));
}
__device__ __forceinline__ void ldsm4(uint32_t& r0, uint32_t& r1, uint32_t& r2, uint32_t& r3,
                                      uint32_t addr) {
    asm volatile("ldmatrix.sync.aligned.m8n8.x4.shared.b16 {%0,%1,%2,%3}, [%4];"
                 : "=r"(r0), "=r"(r1), "=r"(r2), "=r"(r3) : "r"(addr));
}
__device__ __forceinline__ void mma16816(float* c, const uint32_t* a, const uint32_t* b) {
    asm volatile("mma.sync.aligned.m16n8k16.row.col.f32.f16.f16.f32 "
                 "{%0,%1,%2,%3}, {%4,%5,%6,%7}, {%8,%9}, {%0,%1,%2,%3};"
                 : "+f"(c[0]), "+f"(c[1]), "+f"(c[2]), "+f"(c[3])
                 : "r"(a[0]), "r"(a[1]), "r"(a[2]), "r"(a[3]), "r"(b[0]), "r"(b[1]));
}

#define MBARRIER_INIT(addr, cnt) \
    asm volatile("mbarrier.init.shared.b64 [%0], %1;" :: "r"((uint32_t)(addr)), "r"((uint32_t)(cnt)) : "memory")
#define MBARRIER_ARRIVE(addr) \
    asm volatile("mbarrier.arrive.shared.b64 _, [%0];" :: "r"((uint32_t)(addr)) : "memory")
#define CP_ARRIVE(addr) \
    asm volatile("cp.async.mbarrier.arrive.noinc.shared::cta.b64 [%0];" :: "r"((uint32_t)(addr)) : "memory")

#define MBARRIER_WAIT_PARITY(mbar_smem_addr, phase_parity) do { \
    uint32_t _mbar = (uint32_t)(mbar_smem_addr); \
    uint32_t _parity = (uint32_t)(phase_parity); \
    uint32_t _done; \
    asm volatile( \
        "{\n\t" \
        ".reg .pred p;\n\t" \
        "mbarrier.try_wait.parity.acquire.cta.shared::cta.b64 p, [%1], %2;\n\t" \
        "selp.b32 %0, 1, 0, p;\n\t" \
        "}" \
        : "=r"(_done) : "r"(_mbar), "r"(_parity) : "memory"); \
    if (!_done) { \
        asm volatile( \
            "{\n\t" \
            ".reg .pred P1;\n\t" \
            "WAIT_LOOP_%=:\n\t" \
            "mbarrier.try_wait.parity.acquire.cta.shared::cta.b64 P1, [%0], %1, 0x989680;\n\t" \
            "@P1 bra.uni WAIT_DONE_%=;\n\t" \
            "bra.uni WAIT_LOOP_%=;\n\t" \
            "WAIT_DONE_%=:\n\t" \
            "}" \
            :: "r"(_mbar), "r"(_parity) : "memory"); \
    } \
} while(0)

// ---------------- wdq tile: 64x64 transpose + scale + fp16 cast --------------
__device__ __forceinline__ int wswz(int r, int c) {
    return c ^ (((((r >> 4)) ^ (r & 1)) & 3) << 3) ^ ((c & 32) >> 3);
}
__device__ __forceinline__ void wdq_tile(const float* __restrict__ w,
                                         const float* __restrict__ ws,
                                         __half* __restrict__ dst,
                                         int tile, float* tileS) {
    const int t  = threadIdx.x;
    const int n0 = (tile & 63) << 6, k0 = (tile >> 6) << 6;
    const float s = ws[(k0 >> 7) * 32 + (n0 >> 7)];
    if (t < 256) {
        const int kr = t >> 2, c = (t & 3) << 4;
        const float* src = w + (size_t)(k0 + kr) * HDIM + n0 + c;
#pragma unroll
        for (int j = 0; j < 4; ++j) {
            float4 v = *reinterpret_cast<const float4*>(src + 4 * j);
            *reinterpret_cast<float4*>(&tileS[kr * 64 + wswz(kr, c + 4 * j)]) = v;
        }
    }
    __syncthreads();
    if (t < 256) {
        const int n = t >> 2, kc = (t & 3) << 4;
        __half2 hv[8];
#pragma unroll
        for (int u = 0; u < 8; ++u) {
            const int r0 = kc + 2 * u, r1 = r0 + 1;
            hv[u] = __floats2half2_rn(tileS[r0 * 64 + wswz(r0, n)] * s,
                                      tileS[r1 * 64 + wswz(r1, n)] * s);
        }
        uint4* dp = reinterpret_cast<uint4*>(dst + (size_t)(n0 + n) * HDIM + k0 + kc);
        const uint4* hv4 = reinterpret_cast<const uint4*>(hv);
        dp[0] = hv4[0];
        dp[1] = hv4[1];
    }
}

// ------- GEMM: g_resid += g_A @ g_WT[w]^T. BM=BN=128, BK=32, 5-stage mbar ring
// R14 instruction order (consume -> release -> produce); ONLY ring depth changed.
static constexpr int      BK = 32, STAGES = 5;
static constexpr int      NIT = HDIM / BK;                    // 128
static constexpr int      SW  = 40;                           // smem stride (halfs)
static constexpr uint32_t DATA_OFF  = 1024;
static constexpr uint32_t ABYTES    = 128 * SW * 2;           // 10240
static constexpr uint32_t STG_BYTES = 2 * ABYTES;             // 20480 (A + B)
static constexpr uint32_t GEMM_SMEM = DATA_OFF + STAGES * STG_BYTES;  // 103424
static constexpr int      NGEMM_CTAS = 1024;

__global__ void __launch_bounds__(256, 2) gemm_kernel(int which,
                                                      const float* __restrict__ wn,
                                                      const float* __restrict__ wsn) {
    extern __shared__ __half smem[];
    if (blockIdx.x >= NGEMM_CTAS) {
        wdq_tile(wn, wsn, g_WT[which + 1], blockIdx.x - NGEMM_CTAS,
                 reinterpret_cast<float*>(smem));
        return;
    }
    const uint32_t sb = smem_u32(smem);
    const int tid  = threadIdx.x;
    const int lane = tid & 31;
    const int warp = tid >> 5;
    const int m0 = (blockIdx.x >> 5) << 7;   // 32 m-panels
    const int n0 = (blockIdx.x & 31) << 7;   // 32 n-panels
    const int wm = warp & 3;                 // 4 warps along M (32 rows each)
    const int wn2 = warp >> 2;               // 2 warps along N (64 cols each)

    if (tid == 0) {
#pragma unroll
        for (int s = 0; s < STAGES; ++s) {
            MBARRIER_INIT(sb + 8 * s, 256);       // full[s]
            MBARRIER_INIT(sb + 64 + 8 * s, 8);    // empty[s]
        }
    }
    __syncthreads();

    // per-warp producer slice
    const int prow = warp * 16 + (lane >> 1);
    const int pj   = (lane & 1) * 2;
    const __half* gA = g_A + (size_t)(m0 + prow) * HDIM + pj * 8;
    const __half* gB = g_WT[which] + (size_t)(n0 + prow) * HDIM + pj * 8;
    const uint32_t sA = sb + DATA_OFF + (uint32_t)((prow * SW + pj * 8) * 2);
    const uint32_t sB = sA + ABYTES;

#define LOAD_STAGE(it, s) do { \
        const uint32_t _so = (uint32_t)(s) * STG_BYTES; \
        const __half* _a = gA + (size_t)(it) * BK; \
        const __half* _b = gB + (size_t)(it) * BK; \
        cp16(sA + _so,       _a);      \
        cp16(sA + _so + 16,  _a + 8);  \
        cp16(sB + _so,       _b);      \
        cp16(sB + _so + 16,  _b + 8);  \
        CP_ARRIVE(sb + 8 * (s));       \
    } while (0)

    // prologue: produce stages 0..3 (round 0, no empty wait)
    LOAD_STAGE(0, 0);
    LOAD_STAGE(1, 1);
    LOAD_STAGE(2, 2);
    LOAD_STAGE(3, 3);

    float c[2][8][4];
#pragma unroll
    for (int mi = 0; mi < 2; ++mi)
#pragma unroll
        for (int ni = 0; ni < 8; ++ni)
#pragma unroll
            for (int v = 0; v < 4; ++v) c[mi][ni][v] = 0.f;

    // consumer fragment base addresses (stage 0)
    const uint32_t aBase = sb + DATA_OFF +
        (uint32_t)(((wm * 32 + (lane & 15)) * SW + (lane >> 4) * 8) * 2);
    const uint32_t bBase = sb + DATA_OFF + ABYTES +
        (uint32_t)(((wn2 * 64 + ((lane >> 4) & 1) * 8 + (lane & 7)) * SW + ((lane >> 3) & 1) * 8) * 2);

    int cs = 0, cph = 0;          // consumer stage / phase
    int ps = 4, pround = 0;       // producer stage / round
    int pit = 4;                  // next k-iteration to produce

#pragma unroll 1
    for (int it = 0; it < NIT; ++it) {
        // ---- consume stage cs (R14 order: wait-full first) ----
        MBARRIER_WAIT_PARITY(sb + 8 * cs, cph);
        const uint32_t so = (uint32_t)cs * STG_BYTES;
#pragma unroll
        for (int ks = 0; ks < 2; ++ks) {
            uint32_t a[2][4], b[8][2];
#pragma unroll
            for (int mi = 0; mi < 2; ++mi)
                ldsm4(a[mi][0], a[mi][1], a[mi][2], a[mi][3],
                      aBase + so + (uint32_t)(mi * 16 * SW * 2 + ks * 32));
#pragma unroll
            for (int pz = 0; pz < 4; ++pz)
                ldsm4(b[2 * pz][0], b[2 * pz][1], b[2 * pz + 1][0], b[2 * pz + 1][1],
                      bBase + so + (uint32_t)(pz * 16 * SW * 2 + ks * 32));
#pragma unroll
            for (int mi = 0; mi < 2; ++mi)
#pragma unroll
                for (int ni = 0; ni < 8; ++ni)
                    mma16816(c[mi][ni], a[mi], b[ni]);
        }
        __syncwarp();
        if (lane == 0) MBARRIER_ARRIVE(sb + 64 + 8 * cs);  // release stage cs
        if (++cs == STAGES) { cs = 0; cph ^= 1; }

        // ---- produce (R14 order: after consume) ----
        if (pit < NIT) {
            if (pround > 0) MBARRIER_WAIT_PARITY(sb + 64 + 8 * ps, (pround - 1) & 1);
            LOAD_STAGE(pit, ps);
            ++pit;
            if (++ps == STAGES) { ps = 0; ++pround; }
        }
    }

    // epilogue: g_resid += acc (fused residual add)
#pragma unroll
    for (int mi = 0; mi < 2; ++mi) {
        const int row = m0 + wm * 32 + mi * 16 + (lane >> 2);
        float* b0 = g_resid + (size_t)row * HDIM + n0 + wn2 * 64 + 2 * (lane & 3);
        float* b1 = b0 + 8 * HDIM;
#pragma unroll
        for (int ni = 0; ni < 8; ++ni) {
            float2 o0 = *reinterpret_cast<float2*>(b0 + ni * 8);
            float2 o1 = *reinterpret_cast<float2*>(b1 + ni * 8);
            o0.x += c[mi][ni][0]; o0.y += c[mi][ni][1];
            o1.x += c[mi][ni][2]; o1.y += c[mi][ni][3];
            *reinterpret_cast<float2*>(b0 + ni * 8) = o0;
            *reinterpret_cast<float2*>(b1 + ni * 8) = o1;
        }
    }
#undef LOAD_STAGE
}

// -------- norm body: 512 threads, 8 elems/thread ------------------------------
__device__ __forceinline__ void norm_body(const float* __restrict__ xin,
                                          const float* __restrict__ nw,
                                          float* __restrict__ outp, int mode,
                                          int row, float* red) {
    const int t = threadIdx.x;
    const size_t base = (size_t)row * HDIM + t * 8;
    float4 va[2];
    float ss = 0.f;
    if (mode == 0) {
        const float4* px = reinterpret_cast<const float4*>(xin + base);
        float4* pr = reinterpret_cast<float4*>(g_resid + base);
#pragma unroll
        for (int i = 0; i < 2; ++i) {
            float4 a = px[i];
            a.x = fmaxf(a.x, 0.f); a.y = fmaxf(a.y, 0.f);
            a.z = fmaxf(a.z, 0.f); a.w = fmaxf(a.w, 0.f);
            va[i] = a; pr[i] = a;
            ss += a.x * a.x + a.y * a.y + a.z * a.z + a.w * a.w;
        }
    } else {
        const float4* pr = reinterpret_cast<const float4*>(g_resid + base);
#pragma unroll
        for (int i = 0; i < 2; ++i) {
            float4 a = pr[i];
            va[i] = a;
            ss += a.x * a.x + a.y * a.y + a.z * a.z + a.w * a.w;
        }
    }
#pragma unroll
    for (int o = 16; o; o >>= 1) ss += __shfl_down_sync(0xffffffffu, ss, o);
    if ((t & 31) == 0) red[t >> 5] = ss;
    __syncthreads();
    if (t == 0) {
        float s = 0.f;
#pragma unroll
        for (int i = 0; i < 16; ++i) s += red[i];
        red[16] = rsqrtf(s * (1.f / HDIM) + 1e-6f);
    }
    __syncthreads();
    const float r = red[16];

    const float4* pn = reinterpret_cast<const float4*>(nw) + t * 2;
    float y[8];
    float amax = 0.f;
#pragma unroll
    for (int i = 0; i < 2; ++i) {
        float4 a = va[i], w4 = pn[i];
        y[4 * i + 0] = a.x * r * w4.x; y[4 * i + 1] = a.y * r * w4.y;
        y[4 * i + 2] = a.z * r * w4.z; y[4 * i + 3] = a.w * r * w4.w;
        amax = fmaxf(amax, fabsf(y[4 * i + 0])); amax = fmaxf(amax, fabsf(y[4 * i + 1]));
        amax = fmaxf(amax, fabsf(y[4 * i + 2])); amax = fmaxf(amax, fabsf(y[4 * i + 3]));
    }
    if (mode == 2) {
        float4* po = reinterpret_cast<float4*>(outp + base);
        po[0] = make_float4(y[0], y[1], y[2], y[3]);
        po[1] = make_float4(y[4], y[5], y[6], y[7]);
        return;
    }
    amax = fmaxf(amax, __shfl_xor_sync(0xffffffffu, amax, 1));
    amax = fmaxf(amax, __shfl_xor_sync(0xffffffffu, amax, 2));
    amax = fmaxf(amax, __shfl_xor_sync(0xffffffffu, amax, 4));
    amax = fmaxf(amax, __shfl_xor_sync(0xffffffffu, amax, 8));
    const float amc = fmaxf(amax, 4.48e-10f);
    const float s  = amc * (1.f / 448.f);
    const float rs = __fdividef(448.f, amc);
    __half2 hv[4];
#pragma unroll
    for (int j = 0; j < 4; ++j) {
        float2 q = make_float2(y[2 * j] * rs, y[2 * j + 1] * rs);
        __nv_fp8x2_storage_t q2 = __nv_cvt_float2_to_fp8x2(q, __NV_SATFINITE, __NV_E4M3);
        __half2_raw hr = __nv_cvt_fp8x2_to_halfraw2(q2, __NV_E4M3);
        __half2 hq = *reinterpret_cast<__half2*>(&hr);
        float2 qf = __half22float2(hq);
        hv[j] = __floats2half2_rn(qf.x * s, qf.y * s);
    }
    *reinterpret_cast<uint4*>(g_A + base) = *reinterpret_cast<const uint4*>(hv);
}

// standalone norm (modes 1, 2), 512 threads
__global__ void __launch_bounds__(512) k_norm(const float* __restrict__ nw,
                                              float* __restrict__ outp, int mode) {
    __shared__ float red[17];
    norm_body(nullptr, nw, outp, mode, blockIdx.x, red);
}

// merged: norm mode0 (blocks 0..4095, 512 thr) + wdq(w0) (blocks 4096..8191)
__global__ void __launch_bounds__(512) k_norm0_wdq(const float* __restrict__ x,
                                                   const float* __restrict__ nw,
                                                   const float* __restrict__ w,
                                                   const float* __restrict__ ws) {
    __shared__ float sh[64 * 64];
    if (blockIdx.x < 4096) {
        norm_body(x, nw, nullptr, 0, blockIdx.x, sh);
    } else {
        wdq_tile(w, ws, g_WT[0], blockIdx.x - 4096, sh);
    }
}

// ---------------- launch ----------------
extern "C" void kernel_launch(void* const* d_in, const int* in_sizes, int n_in,
                              void* d_out, int out_size) {
    const float* x   = (const float*)d_in[0];
    const float* w0  = (const float*)d_in[1];
    const float* ws0 = (const float*)d_in[2];
    const float* w1  = (const float*)d_in[3];
    const float* ws1 = (const float*)d_in[4];
    const float* w2  = (const float*)d_in[5];
    const float* ws2 = (const float*)d_in[6];
    const float* nw0 = (const float*)d_in[7];
    const float* nw1 = (const float*)d_in[8];
    const float* nw2 = (const float*)d_in[9];
    const float* nw3 = (const float*)d_in[10];
    float* out = (float*)d_out;

    cudaFuncSetAttribute(gemm_kernel, cudaFuncAttributeMaxDynamicSharedMemorySize, GEMM_SMEM);

    k_norm0_wdq<<<8192, 512>>>(x, nw0, w0, ws0);                      // norm0 || wdq(w0)
    gemm_kernel<<<NGEMM_CTAS + 4096, 256, GEMM_SMEM>>>(0, w1, ws1);   // gemm0 + wdq(w1)

    k_norm<<<MTOK, 512>>>(nw1, nullptr, 1);
    gemm_kernel<<<NGEMM_CTAS + 4096, 256, GEMM_SMEM>>>(1, w2, ws2);   // gemm1 + wdq(w2)

    k_norm<<<MTOK, 512>>>(nw2, nullptr, 1);
    gemm_kernel<<<NGEMM_CTAS, 256, GEMM_SMEM>>>(2, nullptr, nullptr); // gemm2 only

    k_norm<<<MTOK, 512>>>(nw3, out, 2);
}

// round 17
// speedup vs baseline: 1.1577x; 1.0303x over previous
#include <cuda_runtime.h>
#include <cuda_fp16.h>
#include <cuda_fp8.h>
#include <cstdint>

#define HDIM 4096
#define MTOK 4096

// ---------------- scratch (device globals; no runtime alloc) ----------------
__device__ float  g_resid[(size_t)MTOK * HDIM];    // 64 MB (GEMM accumulates here)
__device__ __half g_A[(size_t)MTOK * HDIM];        // 32 MB  qdq activations, fp16
__device__ __half g_WT[3][(size_t)HDIM * HDIM];    // 96 MB  scaled weights, [N,K] K-major

// ---------------- PTX helpers (plain compute_103-legal) ----------------
__device__ __forceinline__ uint32_t smem_u32(const void* p) {
    uint32_t a;
    asm("{ .reg .u64 t; cvta.to.shared.u64 t, %1; cvt.u32.u64 %0, t; }" : "=r"(a) : "l"(p));
    return a;
}
__device__ __forceinline__ void cp16(uint32_t s, const void* g) {
    asm volatile("cp.async.cg.shared.global [%0], [%1], 16;" :: "r"(s), "l"(g));
}
__device__ __forceinline__ void ldsm4(uint32_t& r0, uint32_t& r1, uint32_t& r2, uint32_t& r3,
                                      uint32_t addr) {
    asm volatile("ldmatrix.sync.aligned.m8n8.x4.shared.b16 {%0,%1,%2,%3}, [%4];"
                 : "=r"(r0), "=r"(r1), "=r"(r2), "=r"(r3) : "r"(addr));
}
__device__ __forceinline__ void mma16816(float* c, const uint32_t* a, const uint32_t* b) {
    asm volatile("mma.sync.aligned.m16n8k16.row.col.f32.f16.f16.f32 "
                 "{%0,%1,%2,%3}, {%4,%5,%6,%7}, {%8,%9}, {%0,%1,%2,%3};"
                 : "+f"(c[0]), "+f"(c[1]), "+f"(c[2]), "+f"(c[3])
                 : "r"(a[0]), "r"(a[1]), "r"(a[2]), "r"(a[3]), "r"(b[0]), "r"(b[1]));
}

#define MBARRIER_INIT(addr, cnt) \
    asm volatile("mbarrier.init.shared.b64 [%0], %1;" :: "r"((uint32_t)(addr)), "r"((uint32_t)(cnt)) : "memory")
#define MBARRIER_ARRIVE(addr) \
    asm volatile("mbarrier.arrive.shared.b64 _, [%0];" :: "r"((uint32_t)(addr)) : "memory")
#define CP_ARRIVE(addr) \
    asm volatile("cp.async.mbarrier.arrive.noinc.shared::cta.b64 [%0];" :: "r"((uint32_t)(addr)) : "memory")

#define MBARRIER_WAIT_PARITY(mbar_smem_addr, phase_parity) do { \
    uint32_t _mbar = (uint32_t)(mbar_smem_addr); \
    uint32_t _parity = (uint32_t)(phase_parity); \
    uint32_t _done; \
    asm volatile( \
        "{\n\t" \
        ".reg .pred p;\n\t" \
        "mbarrier.try_wait.parity.acquire.cta.shared::cta.b64 p, [%1], %2;\n\t" \
        "selp.b32 %0, 1, 0, p;\n\t" \
        "}" \
        : "=r"(_done) : "r"(_mbar), "r"(_parity) : "memory"); \
    if (!_done) { \
        asm volatile( \
            "{\n\t" \
            ".reg .pred P1;\n\t" \
            "WAIT_LOOP_%=:\n\t" \
            "mbarrier.try_wait.parity.acquire.cta.shared::cta.b64 P1, [%0], %1, 0x989680;\n\t" \
            "@P1 bra.uni WAIT_DONE_%=;\n\t" \
            "bra.uni WAIT_LOOP_%=;\n\t" \
            "WAIT_DONE_%=:\n\t" \
            "}" \
            :: "r"(_mbar), "r"(_parity) : "memory"); \
    } \
} while(0)

// ---------------- wdq tile: 64x64 transpose + scale + fp16 cast --------------
__device__ __forceinline__ int wswz(int r, int c) {
    return c ^ (((((r >> 4)) ^ (r & 1)) & 3) << 3) ^ ((c & 32) >> 3);
}
__device__ __forceinline__ void wdq_tile(const float* __restrict__ w,
                                         const float* __restrict__ ws,
                                         __half* __restrict__ dst,
                                         int tile, float* tileS) {
    const int t  = threadIdx.x;
    const int n0 = (tile & 63) << 6, k0 = (tile >> 6) << 6;
    const float s = ws[(k0 >> 7) * 32 + (n0 >> 7)];
    if (t < 256) {
        const int kr = t >> 2, c = (t & 3) << 4;
        const float* src = w + (size_t)(k0 + kr) * HDIM + n0 + c;
#pragma unroll
        for (int j = 0; j < 4; ++j) {
            float4 v = *reinterpret_cast<const float4*>(src + 4 * j);
            *reinterpret_cast<float4*>(&tileS[kr * 64 + wswz(kr, c + 4 * j)]) = v;
        }
    }
    __syncthreads();
    if (t < 256) {
        const int n = t >> 2, kc = (t & 3) << 4;
        __half2 hv[8];
#pragma unroll
        for (int u = 0; u < 8; ++u) {
            const int r0 = kc + 2 * u, r1 = r0 + 1;
            hv[u] = __floats2half2_rn(tileS[r0 * 64 + wswz(r0, n)] * s,
                                      tileS[r1 * 64 + wswz(r1, n)] * s);
        }
        uint4* dp = reinterpret_cast<uint4*>(dst + (size_t)(n0 + n) * HDIM + k0 + kc);
        const uint4* hv4 = reinterpret_cast<const uint4*>(hv);
        dp[0] = hv4[0];
        dp[1] = hv4[1];
    }
}

// ------- GEMM: g_resid += g_A @ g_WT[w]^T. BM=BN=128, BK=32, 4-stage mbar ring
// R14 instruction order; main loop unrolled by ring depth (stage indices static).
static constexpr int      BK = 32, STAGES = 4;
static constexpr int      SW  = 40;                           // smem stride (halfs)
static constexpr uint32_t DATA_OFF  = 1024;
static constexpr uint32_t ABYTES    = 128 * SW * 2;           // 10240
static constexpr uint32_t STG_BYTES = 2 * ABYTES;             // 20480 (A + B)
static constexpr uint32_t GEMM_SMEM = DATA_OFF + STAGES * STG_BYTES;  // 82944
static constexpr int      NGEMM_CTAS = 1024;
static constexpr int      NROUND = HDIM / BK / STAGES;        // 32

__global__ void __launch_bounds__(256, 2) gemm_kernel(int which,
                                                      const float* __restrict__ wn,
                                                      const float* __restrict__ wsn) {
    extern __shared__ __half smem[];
    if (blockIdx.x >= NGEMM_CTAS) {
        wdq_tile(wn, wsn, g_WT[which + 1], blockIdx.x - NGEMM_CTAS,
                 reinterpret_cast<float*>(smem));
        return;
    }
    const uint32_t sb = smem_u32(smem);
    const int tid  = threadIdx.x;
    const int lane = tid & 31;
    const int warp = tid >> 5;
    const int m0 = (blockIdx.x >> 5) << 7;   // 32 m-panels
    const int n0 = (blockIdx.x & 31) << 7;   // 32 n-panels
    const int wm = warp & 3;                 // 4 warps along M (32 rows each)
    const int wn2 = warp >> 2;               // 2 warps along N (64 cols each)

    if (tid == 0) {
#pragma unroll
        for (int s = 0; s < STAGES; ++s) {
            MBARRIER_INIT(sb + 8 * s, 256);       // full[s]
            MBARRIER_INIT(sb + 64 + 8 * s, 8);    // empty[s]
        }
    }
    __syncthreads();

    // per-warp producer slice
    const int prow = warp * 16 + (lane >> 1);
    const int pj   = (lane & 1) * 2;
    const __half* gA = g_A + (size_t)(m0 + prow) * HDIM + pj * 8;
    const __half* gB = g_WT[which] + (size_t)(n0 + prow) * HDIM + pj * 8;
    const uint32_t sA = sb + DATA_OFF + (uint32_t)((prow * SW + pj * 8) * 2);
    const uint32_t sB = sA + ABYTES;

#define LOAD_STAGE(it, s) do { \
        const uint32_t _so = (uint32_t)(s) * STG_BYTES; \
        const __half* _a = gA + (size_t)(it) * BK; \
        const __half* _b = gB + (size_t)(it) * BK; \
        cp16(sA + _so,       _a);      \
        cp16(sA + _so + 16,  _a + 8);  \
        cp16(sB + _so,       _b);      \
        cp16(sB + _so + 16,  _b + 8);  \
        CP_ARRIVE(sb + 8 * (s));       \
    } while (0)

    // prologue: produce stages 0..2 (round 0, no empty wait)
    LOAD_STAGE(0, 0);
    LOAD_STAGE(1, 1);
    LOAD_STAGE(2, 2);

    float c[2][8][4];
#pragma unroll
    for (int mi = 0; mi < 2; ++mi)
#pragma unroll
        for (int ni = 0; ni < 8; ++ni)
#pragma unroll
            for (int v = 0; v < 4; ++v) c[mi][ni][v] = 0.f;

    // consumer fragment base addresses (stage 0)
    const uint32_t aBase = sb + DATA_OFF +
        (uint32_t)(((wm * 32 + (lane & 15)) * SW + (lane >> 4) * 8) * 2);
    const uint32_t bBase = sb + DATA_OFF + ABYTES +
        (uint32_t)(((wn2 * 64 + ((lane >> 4) & 1) * 8 + (lane & 7)) * SW + ((lane >> 3) & 1) * 8) * 2);

    // consume body for stage S (compile-time), iteration index 4*r+S
#define CONSUME_STAGE(S) do { \
        const uint32_t _so = (uint32_t)(S) * STG_BYTES; \
        _Pragma("unroll") \
        for (int ks = 0; ks < 2; ++ks) { \
            uint32_t a[2][4], b[8][2]; \
            _Pragma("unroll") \
            for (int mi = 0; mi < 2; ++mi) \
                ldsm4(a[mi][0], a[mi][1], a[mi][2], a[mi][3], \
                      aBase + _so + (uint32_t)(mi * 16 * SW * 2 + ks * 32)); \
            _Pragma("unroll") \
            for (int pz = 0; pz < 4; ++pz) \
                ldsm4(b[2 * pz][0], b[2 * pz][1], b[2 * pz + 1][0], b[2 * pz + 1][1], \
                      bBase + _so + (uint32_t)(pz * 16 * SW * 2 + ks * 32)); \
            _Pragma("unroll") \
            for (int mi = 0; mi < 2; ++mi) \
                _Pragma("unroll") \
                for (int ni = 0; ni < 8; ++ni) \
                    mma16816(c[mi][ni], a[mi], b[ni]); \
        } \
    } while (0)

    // full iteration for stage S in round r (R14 order: wait -> consume -> release -> produce)
#define ITER_STAGE(S, r, ph, prod) do { \
        MBARRIER_WAIT_PARITY(sb + 8 * (S), (ph)); \
        CONSUME_STAGE(S); \
        __syncwarp(); \
        if (lane == 0) MBARRIER_ARRIVE(sb + 64 + 8 * (S)); \
        if (prod) { \
            MBARRIER_WAIT_PARITY(sb + 64 + 8 * (S), (ph)); \
            LOAD_STAGE(4 * (r) + (S) + STAGES - 1, (S)); \
        } \
    } while (0)

    // NOTE: stage S in round r holds k-iteration 4r+S; producer refills stage S
    // with k-iteration 4r+S+4... but prologue only filled 0..2, so stage 3 of
    // round 0 is produced by the first produce slot. Mapping: produce target for
    // (r, S) slot is iteration 4r+S+3 into stage (S+3)&3 — keep R14's exact
    // mapping instead: produce iteration p = it+3 into stage p&3.
#undef ITER_STAGE
#define ITER_STAGE(S, r, ph) do { \
        MBARRIER_WAIT_PARITY(sb + 8 * (S), (ph)); \
        CONSUME_STAGE(S); \
        __syncwarp(); \
        if (lane == 0) MBARRIER_ARRIVE(sb + 64 + 8 * (S)); \
        { \
            const int _p  = 4 * (r) + (S) + 3;            /* produce iteration */ \
            const int _sp = _p & 3;                       /* = (S+3)&3, static */ \
            const int _pr = _p >> 2;                      /* producer round   */ \
            if (_p < HDIM / BK) { \
                if (_pr > 0) MBARRIER_WAIT_PARITY(sb + 64 + 8 * _sp, (_pr - 1) & 1); \
                LOAD_STAGE(_p, _sp); \
            } \
        } \
    } while (0)

#pragma unroll 1
    for (int r = 0; r < NROUND; ++r) {
        const uint32_t ph = (uint32_t)(r & 1);
        ITER_STAGE(0, r, ph);
        ITER_STAGE(1, r, ph);
        ITER_STAGE(2, r, ph);
        ITER_STAGE(3, r, ph);
    }

    // epilogue: g_resid += acc (fused residual add)
#pragma unroll
    for (int mi = 0; mi < 2; ++mi) {
        const int row = m0 + wm * 32 + mi * 16 + (lane >> 2);
        float* b0 = g_resid + (size_t)row * HDIM + n0 + wn2 * 64 + 2 * (lane & 3);
        float* b1 = b0 + 8 * HDIM;
#pragma unroll
        for (int ni = 0; ni < 8; ++ni) {
            float2 o0 = *reinterpret_cast<float2*>(b0 + ni * 8);
            float2 o1 = *reinterpret_cast<float2*>(b1 + ni * 8);
            o0.x += c[mi][ni][0]; o0.y += c[mi][ni][1];
            o1.x += c[mi][ni][2]; o1.y += c[mi][ni][3];
            *reinterpret_cast<float2*>(b0 + ni * 8) = o0;
            *reinterpret_cast<float2*>(b1 + ni * 8) = o1;
        }
    }
#undef LOAD_STAGE
#undef CONSUME_STAGE
#undef ITER_STAGE
}

// -------- norm body: 512 threads, 8 elems/thread ------------------------------
__device__ __forceinline__ void norm_body(const float* __restrict__ xin,
                                          const float* __restrict__ nw,
                                          float* __restrict__ outp, int mode,
                                          int row, float* red) {
    const int t = threadIdx.x;
    const size_t base = (size_t)row * HDIM + t * 8;
    float4 va[2];
    float ss = 0.f;
    if (mode == 0) {
        const float4* px = reinterpret_cast<const float4*>(xin + base);
        float4* pr = reinterpret_cast<float4*>(g_resid + base);
#pragma unroll
        for (int i = 0; i < 2; ++i) {
            float4 a = px[i];
            a.x = fmaxf(a.x, 0.f); a.y = fmaxf(a.y, 0.f);
            a.z = fmaxf(a.z, 0.f); a.w = fmaxf(a.w, 0.f);
            va[i] = a; pr[i] = a;
            ss += a.x * a.x + a.y * a.y + a.z * a.z + a.w * a.w;
        }
    } else {
        const float4* pr = reinterpret_cast<const float4*>(g_resid + base);
#pragma unroll
        for (int i = 0; i < 2; ++i) {
            float4 a = pr[i];
            va[i] = a;
            ss += a.x * a.x + a.y * a.y + a.z * a.z + a.w * a.w;
        }
    }
#pragma unroll
    for (int o = 16; o; o >>= 1) ss += __shfl_down_sync(0xffffffffu, ss, o);
    if ((t & 31) == 0) red[t >> 5] = ss;
    __syncthreads();
    if (t == 0) {
        float s = 0.f;
#pragma unroll
        for (int i = 0; i < 16; ++i) s += red[i];
        red[16] = rsqrtf(s * (1.f / HDIM) + 1e-6f);
    }
    __syncthreads();
    const float r = red[16];

    const float4* pn = reinterpret_cast<const float4*>(nw) + t * 2;
    float y[8];
    float amax = 0.f;
#pragma unroll
    for (int i = 0; i < 2; ++i) {
        float4 a = va[i], w4 = pn[i];
        y[4 * i + 0] = a.x * r * w4.x; y[4 * i + 1] = a.y * r * w4.y;
        y[4 * i + 2] = a.z * r * w4.z; y[4 * i + 3] = a.w * r * w4.w;
        amax = fmaxf(amax, fabsf(y[4 * i + 0])); amax = fmaxf(amax, fabsf(y[4 * i + 1]));
        amax = fmaxf(amax, fabsf(y[4 * i + 2])); amax = fmaxf(amax, fabsf(y[4 * i + 3]));
    }
    if (mode == 2) {
        float4* po = reinterpret_cast<float4*>(outp + base);
        po[0] = make_float4(y[0], y[1], y[2], y[3]);
        po[1] = make_float4(y[4], y[5], y[6], y[7]);
        return;
    }
    amax = fmaxf(amax, __shfl_xor_sync(0xffffffffu, amax, 1));
    amax = fmaxf(amax, __shfl_xor_sync(0xffffffffu, amax, 2));
    amax = fmaxf(amax, __shfl_xor_sync(0xffffffffu, amax, 4));
    amax = fmaxf(amax, __shfl_xor_sync(0xffffffffu, amax, 8));
    const float amc = fmaxf(amax, 4.48e-10f);
    const float s  = amc * (1.f / 448.f);
    const float rs = __fdividef(448.f, amc);
    __half2 hv[4];
#pragma unroll
    for (int j = 0; j < 4; ++j) {
        float2 q = make_float2(y[2 * j] * rs, y[2 * j + 1] * rs);
        __nv_fp8x2_storage_t q2 = __nv_cvt_float2_to_fp8x2(q, __NV_SATFINITE, __NV_E4M3);
        __half2_raw hr = __nv_cvt_fp8x2_to_halfraw2(q2, __NV_E4M3);
        __half2 hq = *reinterpret_cast<__half2*>(&hr);
        float2 qf = __half22float2(hq);
        hv[j] = __floats2half2_rn(qf.x * s, qf.y * s);
    }
    *reinterpret_cast<uint4*>(g_A + base) = *reinterpret_cast<const uint4*>(hv);
}

// standalone norm (modes 1, 2), 512 threads
__global__ void __launch_bounds__(512) k_norm(const float* __restrict__ nw,
                                              float* __restrict__ outp, int mode) {
    __shared__ float red[17];
    norm_body(nullptr, nw, outp, mode, blockIdx.x, red);
}

// merged: norm mode0 (blocks 0..4095, 512 thr) + wdq(w0) (blocks 4096..8191)
__global__ void __launch_bounds__(512) k_norm0_wdq(const float* __restrict__ x,
                                                   const float* __restrict__ nw,
                                                   const float* __restrict__ w,
                                                   const float* __restrict__ ws) {
    __shared__ float sh[64 * 64];
    if (blockIdx.x < 4096) {
        norm_body(x, nw, nullptr, 0, blockIdx.x, sh);
    } else {
        wdq_tile(w, ws, g_WT[0], blockIdx.x - 4096, sh);
    }
}

// ---------------- launch ----------------
extern "C" void kernel_launch(void* const* d_in, const int* in_sizes, int n_in,
                              void* d_out, int out_size) {
    const float* x   = (const float*)d_in[0];
    const float* w0  = (const float*)d_in[1];
    const float* ws0 = (const float*)d_in[2];
    const float* w1  = (const float*)d_in[3];
    const float* ws1 = (const float*)d_in[4];
    const float* w2  = (const float*)d_in[5];
    const float* ws2 = (const float*)d_in[6];
    const float* nw0 = (const float*)d_in[7];
    const float* nw1 = (const float*)d_in[8];
    const float* nw2 = (const float*)d_in[9];
    const float* nw3 = (const float*)d_in[10];
    float* out = (float*)d_out;

    cudaFuncSetAttribute(gemm_kernel, cudaFuncAttributeMaxDynamicSharedMemorySize, GEMM_SMEM);

    k_norm0_wdq<<<8192, 512>>>(x, nw0, w0, ws0);                      // norm0 || wdq(w0)
    gemm_kernel<<<NGEMM_CTAS + 4096, 256, GEMM_SMEM>>>(0, w1, ws1);   // gemm0 + wdq(w1)

    k_norm<<<MTOK, 512>>>(nw1, nullptr, 1);
    gemm_kernel<<<NGEMM_CTAS + 4096, 256, GEMM_SMEM>>>(1, w2, ws2);   // gemm1 + wdq(w2)

    k_norm<<<MTOK, 512>>>(nw2, nullptr, 1);
    gemm_kernel<<<NGEMM_CTAS, 256, GEMM_SMEM>>>(2, nullptr, nullptr); // gemm2 only

    k_norm<<<MTOK, 512>>>(nw3, out, 2);
}